// round 9
// baseline (speedup 1.0000x reference)
#include <cuda_runtime.h>

#define NN 32
#define CC 1024
#define NT 1024
#define FULLM 0xffffffffu

// dynamic smem layout
#define OFF_ROWS 0                      // float [32][1024]  = 131072
#define OFF_D    131072                 // float [32][32]    = 4096
#define OFF_MROW 135168                 // float [1024]      = 4096
#define OFF_VAL  139264                 // u32   [2][32]     = 256
#define OFF_IDX  139520                 // u32   [2][32]     = 256
#define OFF_SQ   139776                 // float [32]        = 128
#define OFF_L    139904                 // int   [32]        = 128
#define SMEM_TOTAL 140032

typedef unsigned long long u64;

__device__ __forceinline__ float warp_sum(float v) {
    #pragma unroll
    for (int o = 16; o; o >>= 1) v += __shfl_down_sync(FULLM, v, o);
    return v;
}

__device__ __forceinline__ void warp_sum4(float& a, float& b, float& c, float& d) {
    #pragma unroll
    for (int o = 16; o; o >>= 1) {
        a += __shfl_down_sync(FULLM, a, o);
        b += __shfl_down_sync(FULLM, b, o);
        c += __shfl_down_sync(FULLM, c, o);
        d += __shfl_down_sync(FULLM, d, o);
    }
}

__global__ __launch_bounds__(NT, 1)
void merge_tree_kernel(const float* __restrict__ x,
                       const float* __restrict__ cw,
                       const float* __restrict__ cb,
                       float* __restrict__ out)
{
    extern __shared__ unsigned char sm_raw[];
    float*    rows = (float*)(sm_raw + OFF_ROWS);
    float*    D    = (float*)(sm_raw + OFF_D);
    float*    mrow = (float*)(sm_raw + OFF_MROW);
    unsigned* vals = (unsigned*)(sm_raw + OFF_VAL);   // [2][32]
    unsigned* idxs = (unsigned*)(sm_raw + OFF_IDX);   // [2][32]
    float*    sq   = (float*)(sm_raw + OFF_SQ);
    int*      L    = (int*)(sm_raw + OFF_L);

    const int tid  = threadIdx.x;
    const int lane = tid & 31;
    const int warp = tid >> 5;
    const int b    = blockIdx.x;

    // ---- load batch rows (coalesced float4) ----
    {
        const float4* xb4 = (const float4*)(x + (size_t)b * (NN * CC));
        float4* r4 = (float4*)rows;
        #pragma unroll
        for (int i = tid; i < NN * CC / 4; i += NT) r4[i] = xb4[i];
    }
    const float w00 = cw[0], w01 = cw[1], w02 = cw[2];
    const float w10 = cw[3], w11 = cw[4], w12 = cw[5];
    const float bv  = cb[0];
    if (tid < NN) L[tid] = tid;
    __syncthreads();

    // ---- cache own row in registers; norms (fp32, 4-chain) ----
    float4 rv[8];
    {
        const float4* r4w = (const float4*)(rows + warp * CC);
        #pragma unroll
        for (int k = 0; k < 8; k++) rv[k] = r4w[lane + 32 * k];
        float a0 = 0, a1 = 0, a2 = 0, a3 = 0;
        #pragma unroll
        for (int k = 0; k < 8; k++) {
            a0 = fmaf(rv[k].x, rv[k].x, a0);
            a1 = fmaf(rv[k].y, rv[k].y, a1);
            a2 = fmaf(rv[k].z, rv[k].z, a2);
            a3 = fmaf(rv[k].w, rv[k].w, a3);
        }
        float s = warp_sum((a0 + a1) + (a2 + a3));
        if (!lane) sq[warp] = s;
    }
    __syncthreads();

    // ---- initial gram, balanced rotation (each unordered pair once) ----
    {
        const float sqi = sq[warp];
        #pragma unroll 1
        for (int k = 1; k <= 16; k++) {
            if (k == 16 && warp >= 16) break;
            const int j = (warp + k) & 31;
            const float4* rj4 = (const float4*)(rows + j * CC);
            float a0 = 0, a1 = 0, a2 = 0, a3 = 0;
            #pragma unroll
            for (int q = 0; q < 8; q++) {
                float4 v = rj4[lane + 32 * q];
                a0 = fmaf(rv[q].x, v.x, a0);
                a1 = fmaf(rv[q].y, v.y, a1);
                a2 = fmaf(rv[q].z, v.z, a2);
                a3 = fmaf(rv[q].w, v.w, a3);
            }
            float dot = warp_sum((a0 + a1) + (a2 + a3));
            if (!lane) {
                float d2 = sqi + sq[j] - 2.0f * dot;
                float d  = sqrtf(fmaxf(d2, 0.f));
                D[warp * NN + j] = d;
                D[j * NN + warp] = d;
            }
        }
    }
    __syncthreads();

    // ---- pre-loop argmin partials into buffer 0 ----
    {
        unsigned kv = FULLM, ki = 0x3ffu;
        if (lane > warp) {
            kv = __float_as_uint(D[warp * NN + lane]);
            ki = (unsigned)((warp << 5) | lane);
        }
        unsigned wv = __reduce_min_sync(FULLM, kv);
        unsigned mm = __ballot_sync(FULLM, kv == wv);
        unsigned ci = ((mm >> lane) & 1) ? ki : FULLM;
        unsigned wi = __reduce_min_sync(FULLM, ci);
        if (!lane) { vals[warp] = wv; idxs[warp] = wi; }
    }
    __syncthreads();

    // ==== 31 merge steps, 2 barriers each ====
    int n = NN;
    int par = 0;
    for (int step = 0; step < NN - 1; step++, n--) {
        unsigned* vcur = vals + par * 32;
        unsigned* icur = idxs + par * 32;
        par ^= 1;
        unsigned* vnxt = vals + par * 32;
        unsigned* inxt = idxs + par * 32;

        // ---------- PHASE X ----------
        // combine 32 partials -> global (value, lexicographic idx) min
        unsigned v  = vcur[lane];
        unsigned gm = __reduce_min_sync(FULLM, v);
        unsigned mk = __ballot_sync(FULLM, v == gm);
        unsigned cd = ((mk >> lane) & 1) ? icur[lane] : FULLM;
        unsigned gi = __reduce_min_sync(FULLM, cd);

        const int a   = (gi >> 5) & 31;
        const int bbj = gi & 31;
        const int ra  = L[a];
        const int rb  = L[bbj];
        const int dst = L[(a == 1) ? 0 : a];     // freed slot hosts merged row

        // conv1d(2ch->1ch,k=3,SAME)+bias+relu into register + staging buffer
        const float* Xa = rows + ra * CC;
        const float* Xb = rows + rb * CC;
        const int h = tid;
        float a1v = Xa[h], b1v = Xb[h];
        float a0v = (h > 0)      ? Xa[h - 1] : 0.f;
        float a2v = (h < CC - 1) ? Xa[h + 1] : 0.f;
        float b0v = (h > 0)      ? Xb[h - 1] : 0.f;
        float b2v = (h < CC - 1) ? Xb[h + 1] : 0.f;
        float m = fmaf(w00, a0v, fmaf(w01, a1v, fmaf(w02, a2v,
                  fmaf(w10, b0v, fmaf(w11, b1v, fmaf(w12, b2v, bv))))));
        m = fmaxf(m, 0.f);
        mrow[tid] = m;

        // next logical->slot entry for this tid (from OLD L)
        int newv = 0;
        if (tid < n - 1) {
            if (tid == 0) newv = dst;
            else {
                int pp  = tid + 1;
                int src = (pp == a) ? 0 : ((pp == bbj) ? 1 : pp);
                newv = L[src];
            }
        }

        const int cnt = n - 2;                   // next-config survivors 1..cnt
        const int nw  = (cnt + 2) / 3;           // dot warps

        int s0 = 0, s1 = 0, s2 = 0, c1ok = 0, c2ok = 0, j0 = 0;
        if (warp < nw) {
            // survivor slots from OLD L (Lnext[1+j] = L[src(2+j)])
            j0 = 3 * warp;
            c1ok = (j0 + 1 < cnt);
            c2ok = (j0 + 2 < cnt);
            int p0 = 2 + j0;
            int p1 = p0 + 1;
            int p2 = p0 + 2;
            s0 = L[(p0 == a) ? 0 : ((p0 == bbj) ? 1 : p0)];
            s1 = c1ok ? L[(p1 == a) ? 0 : ((p1 == bbj) ? 1 : p1)] : s0;
            s2 = c2ok ? L[(p2 == a) ? 0 : ((p2 == bbj) ? 1 : p2)] : s0;
        } else if (cnt > 0) {
            // survivor-survivor argmin partials for next config (D stable here)
            const int lok = (lane >= 1) && (lane <= cnt);   // bounds pl <= 31
            const int pl  = lane + 1;
            const int sl  = lok ? L[(pl == a) ? 0 : ((pl == bbj) ? 1 : pl)] : 0;
            u64 kk = 0xffffffffffffffffull;
            const int S = 32 - nw;
            for (int i = 1 + (warp - nw); i <= cnt - 1; i += S) {
                const int pi2 = i + 1;
                const int si = L[(pi2 == a) ? 0 : ((pi2 == bbj) ? 1 : pi2)];
                if (lok && lane > i) {
                    float d = D[si * NN + sl];
                    u64 kc = ((u64)__float_as_uint(d) << 32)
                           | (unsigned)((i << 5) | lane);
                    kk = min(kk, kc);
                }
            }
            unsigned kv = (unsigned)(kk >> 32);
            unsigned wv = __reduce_min_sync(FULLM, kv);
            unsigned mm = __ballot_sync(FULLM, kv == wv);
            unsigned ci = ((mm >> lane) & 1) ? (unsigned)(kk & FULLM) : FULLM;
            unsigned wi = __reduce_min_sync(FULLM, ci);
            if (!lane) { vnxt[warp] = wv; inxt[warp] = wi & 0x3ffu; }
        }
        __syncthreads();                         // bar 1

        // ---------- PHASE Y ----------
        rows[dst * CC + h] = m;                  // commit merged row
        if (tid < n - 1) L[tid] = newv;          // commit next map

        if (warp < nw) {
            const float4* rm  = (const float4*)mrow;
            const float4* rs0 = (const float4*)(rows + s0 * CC);
            const float4* rs1 = (const float4*)(rows + s1 * CC);
            const float4* rs2 = (const float4*)(rows + s2 * CC);
            float A0=0,A1=0,A2=0,A3=0;
            float B0=0,B1=0,B2=0,B3=0;
            float C0=0,C1=0,C2=0,C3=0;
            float M0=0,M1=0,M2=0,M3=0;
            #pragma unroll
            for (int k = 0; k < 8; k++) {
                float4 u  = rm [lane + 32 * k];
                float4 v0 = rs0[lane + 32 * k];
                float4 v1 = rs1[lane + 32 * k];
                float4 v2 = rs2[lane + 32 * k];
                A0 = fmaf(u.x, v0.x, A0);
                A1 = fmaf(u.y, v0.y, A1);
                A2 = fmaf(u.z, v0.z, A2);
                A3 = fmaf(u.w, v0.w, A3);
                B0 = fmaf(u.x, v1.x, B0);
                B1 = fmaf(u.y, v1.y, B1);
                B2 = fmaf(u.z, v1.z, B2);
                B3 = fmaf(u.w, v1.w, B3);
                C0 = fmaf(u.x, v2.x, C0);
                C1 = fmaf(u.y, v2.y, C1);
                C2 = fmaf(u.z, v2.z, C2);
                C3 = fmaf(u.w, v2.w, C3);
                M0 = fmaf(u.x, u.x, M0);
                M1 = fmaf(u.y, u.y, M1);
                M2 = fmaf(u.z, u.z, M2);
                M3 = fmaf(u.w, u.w, M3);
            }
            float d0  = (A0 + A1) + (A2 + A3);
            float d1  = (B0 + B1) + (B2 + B3);
            float d2s = (C0 + C1) + (C2 + C3);
            float msq = (M0 + M1) + (M2 + M3);
            warp_sum4(d0, d1, d2s, msq);
            if (!lane) {
                float e0 = sqrtf(fmaxf(msq + sq[s0] - 2.0f * d0, 0.f));
                D[dst * NN + s0] = e0;
                D[s0 * NN + dst] = e0;
                u64 kk = ((u64)__float_as_uint(e0) << 32) | (unsigned)(1 + j0);
                if (c1ok) {
                    float e1 = sqrtf(fmaxf(msq + sq[s1] - 2.0f * d1, 0.f));
                    D[dst * NN + s1] = e1;
                    D[s1 * NN + dst] = e1;
                    u64 k1 = ((u64)__float_as_uint(e1) << 32) | (unsigned)(2 + j0);
                    kk = min(kk, k1);
                }
                if (c2ok) {
                    float e2 = sqrtf(fmaxf(msq + sq[s2] - 2.0f * d2s, 0.f));
                    D[dst * NN + s2] = e2;
                    D[s2 * NN + dst] = e2;
                    u64 k2 = ((u64)__float_as_uint(e2) << 32) | (unsigned)(3 + j0);
                    kk = min(kk, k2);
                }
                if (warp == 0) sq[dst] = msq;    // persist merged norm
                vnxt[warp] = (unsigned)(kk >> 32);
                inxt[warp] = (unsigned)(kk & 0x3ffu);
            }
        }
        __syncthreads();                         // bar 2
    }

    // final merged row lives at slot L[0]
    out[(size_t)b * CC + tid] = rows[L[0] * CC + tid];
}

extern "C" void kernel_launch(void* const* d_in, const int* in_sizes, int n_in,
                              void* d_out, int out_size)
{
    const float* x  = (const float*)d_in[0];
    const float* cw = (const float*)d_in[1];
    const float* cb = (const float*)d_in[2];
    float* out = (float*)d_out;

    int B = in_sizes[0] / (NN * CC);

    cudaFuncSetAttribute(merge_tree_kernel,
                         cudaFuncAttributeMaxDynamicSharedMemorySize,
                         SMEM_TOTAL);
    merge_tree_kernel<<<B, NT, SMEM_TOTAL>>>(x, cw, cb, out);
}

// round 11
// speedup vs baseline: 1.1442x; 1.1442x over previous
#include <cuda_runtime.h>

#define NN 32
#define DS 33                           // D stride (33 physical slots)
#define CC 1024
#define NT 1024
#define FULLM 0xffffffffu

// dynamic smem layout
#define OFF_ROWS 0                      // float [33][1024]  = 135168
#define OFF_D    135168                 // float [33][33]    = 4356 -> pad 4480
#define OFF_VAL  139648                 // u32   [2][32]     = 256
#define OFF_IDX  139904                 // u32   [2][32]     = 256
#define OFF_SQ   140160                 // float [33]        = 132 -> pad 160
#define OFF_L    140320                 // int   [2][32]     = 256
#define SMEM_TOTAL 140576

typedef unsigned long long u64;

__device__ __forceinline__ float warp_sum(float v) {
    #pragma unroll
    for (int o = 16; o; o >>= 1) v += __shfl_down_sync(FULLM, v, o);
    return v;
}

__device__ __forceinline__ void warp_sum2(float& a, float& b) {
    #pragma unroll
    for (int o = 16; o; o >>= 1) {
        a += __shfl_down_sync(FULLM, a, o);
        b += __shfl_down_sync(FULLM, b, o);
    }
}

__global__ __launch_bounds__(NT, 1)
void merge_tree_kernel(const float* __restrict__ x,
                       const float* __restrict__ cw,
                       const float* __restrict__ cb,
                       float* __restrict__ out)
{
    extern __shared__ unsigned char sm_raw[];
    float*    rows = (float*)(sm_raw + OFF_ROWS);
    float*    D    = (float*)(sm_raw + OFF_D);        // [33][33], stride DS
    unsigned* vals = (unsigned*)(sm_raw + OFF_VAL);   // [2][32]
    unsigned* idxs = (unsigned*)(sm_raw + OFF_IDX);   // [2][32]
    float*    sq   = (float*)(sm_raw + OFF_SQ);       // [33]
    int*      Lb   = (int*)(sm_raw + OFF_L);          // [2][32]

    const int tid  = threadIdx.x;
    const int lane = tid & 31;
    const int warp = tid >> 5;
    const int b    = blockIdx.x;

    // ---- load batch rows (coalesced float4) ----
    {
        const float4* xb4 = (const float4*)(x + (size_t)b * (NN * CC));
        float4* r4 = (float4*)rows;
        #pragma unroll
        for (int i = tid; i < NN * CC / 4; i += NT) r4[i] = xb4[i];
    }
    const float w00 = cw[0], w01 = cw[1], w02 = cw[2];
    const float w10 = cw[3], w11 = cw[4], w12 = cw[5];
    const float bv  = cb[0];
    if (tid < NN) Lb[tid] = tid;                      // L buffer 0
    __syncthreads();

    // ---- cache own row in registers; norms (fp32, 4-chain) ----
    float4 rv[8];
    {
        const float4* r4w = (const float4*)(rows + warp * CC);
        #pragma unroll
        for (int k = 0; k < 8; k++) rv[k] = r4w[lane + 32 * k];
        float a0 = 0, a1 = 0, a2 = 0, a3 = 0;
        #pragma unroll
        for (int k = 0; k < 8; k++) {
            a0 = fmaf(rv[k].x, rv[k].x, a0);
            a1 = fmaf(rv[k].y, rv[k].y, a1);
            a2 = fmaf(rv[k].z, rv[k].z, a2);
            a3 = fmaf(rv[k].w, rv[k].w, a3);
        }
        float s = warp_sum((a0 + a1) + (a2 + a3));
        if (!lane) sq[warp] = s;
    }
    __syncthreads();

    // ---- initial gram, balanced rotation (each unordered pair once;
    //      FMA commutes so values match canonical order) ----
    {
        const float sqi = sq[warp];
        #pragma unroll 1
        for (int k = 1; k <= 16; k++) {
            if (k == 16 && warp >= 16) break;
            const int j = (warp + k) & 31;
            const float4* rj4 = (const float4*)(rows + j * CC);
            float a0 = 0, a1 = 0, a2 = 0, a3 = 0;
            #pragma unroll
            for (int q = 0; q < 8; q++) {
                float4 v = rj4[lane + 32 * q];
                a0 = fmaf(rv[q].x, v.x, a0);
                a1 = fmaf(rv[q].y, v.y, a1);
                a2 = fmaf(rv[q].z, v.z, a2);
                a3 = fmaf(rv[q].w, v.w, a3);
            }
            float dot = warp_sum((a0 + a1) + (a2 + a3));
            if (!lane) {
                float d2 = sqi + sq[j] - 2.0f * dot;
                float d  = sqrtf(fmaxf(d2, 0.f));
                D[warp * DS + j] = d;
                D[j * DS + warp] = d;
            }
        }
    }
    __syncthreads();

    // ---- pre-loop argmin partials into buffer 0 ----
    {
        unsigned kv = FULLM, ki = 0x3ffu;
        if (lane > warp) {
            kv = __float_as_uint(D[warp * DS + lane]);
            ki = (unsigned)((warp << 5) | lane);
        }
        unsigned wv = __reduce_min_sync(FULLM, kv);
        unsigned mm = __ballot_sync(FULLM, kv == wv);
        unsigned ci = ((mm >> lane) & 1) ? ki : FULLM;
        unsigned wi = __reduce_min_sync(FULLM, ci);
        if (!lane) { vals[warp] = wv; idxs[warp] = wi; }
    }
    __syncthreads();

    // ==== 31 merge steps, 2 barriers each (spare-slot, no WAR) ====
    int n = NN;
    int par = 0;        // argmin partial parity
    int lpar = 0;       // L parity
    int spare = 32;     // always-free physical slot
    for (int step = 0; step < NN - 1; step++, n--) {
        unsigned* vcur = vals + par * 32;
        unsigned* icur = idxs + par * 32;
        par ^= 1;
        unsigned* vnxt = vals + par * 32;
        unsigned* inxt = idxs + par * 32;
        int* Lcur = Lb + lpar * 32;
        lpar ^= 1;
        int* Lnxt = Lb + lpar * 32;

        // ---------- P1 ----------
        // combine 32 partials -> global (value, lexicographic idx) min
        unsigned v  = vcur[lane];
        unsigned gm = __reduce_min_sync(FULLM, v);
        unsigned mk = __ballot_sync(FULLM, v == gm);
        unsigned cd = ((mk >> lane) & 1) ? icur[lane] : FULLM;
        unsigned gi = __reduce_min_sync(FULLM, cd);

        const int a   = (gi >> 5) & 31;
        const int bbj = gi & 31;
        const int ra  = Lcur[a];
        const int rb  = Lcur[bbj];
        const int dst = spare;                    // merged row -> spare slot
        // freed slot: normally L[a]; when a==1 the reference's sequential
        // perm-sets drop logical row 0 and KEEP row 1 (ra stays live at
        // position bb), so the freed slot is L[0].
        spare = (a == 1) ? Lcur[0] : ra;

        // conv1d(2ch->1ch,k=3,SAME)+bias+relu, one elem/thread
        const float* Xa = rows + ra * CC;
        const float* Xb = rows + rb * CC;
        const int h = tid;
        float a1v = Xa[h], b1v = Xb[h];
        float a0v = (h > 0)      ? Xa[h - 1] : 0.f;
        float a2v = (h < CC - 1) ? Xa[h + 1] : 0.f;
        float b0v = (h > 0)      ? Xb[h - 1] : 0.f;
        float b2v = (h < CC - 1) ? Xb[h + 1] : 0.f;
        float m = fmaf(w00, a0v, fmaf(w01, a1v, fmaf(w02, a2v,
                  fmaf(w10, b0v, fmaf(w11, b1v, fmaf(w12, b2v, bv))))));
        m = fmaxf(m, 0.f);
        rows[dst * CC + h] = m;                   // no WAR: dst was spare

        if (tid < n - 1) {
            int nv;
            if (tid == 0) nv = dst;
            else {
                int pp  = tid + 1;
                int src = (pp == a) ? 0 : ((pp == bbj) ? 1 : pp);
                nv = Lcur[src];
            }
            Lnxt[tid] = nv;
        }
        __syncthreads();                          // bar 1: rows[dst], Lnxt visible

        // ---------- P2 ----------
        const int cnt = n - 2;                    // next-config survivors 1..cnt
        if (warp < cnt) {
            // one survivor per warp: dot(m, s) + |m|^2, write D + partial
            const int s = Lnxt[1 + warp];
            const float4* rm = (const float4*)(rows + dst * CC);
            const float4* rs = (const float4*)(rows + s * CC);
            float A0 = 0, A1 = 0, A2 = 0, A3 = 0;
            float M0 = 0, M1 = 0, M2 = 0, M3 = 0;
            #pragma unroll
            for (int k = 0; k < 8; k++) {
                float4 u = rm[lane + 32 * k];
                float4 w = rs[lane + 32 * k];
                A0 = fmaf(u.x, w.x, A0);
                A1 = fmaf(u.y, w.y, A1);
                A2 = fmaf(u.z, w.z, A2);
                A3 = fmaf(u.w, w.w, A3);
                M0 = fmaf(u.x, u.x, M0);
                M1 = fmaf(u.y, u.y, M1);
                M2 = fmaf(u.z, u.z, M2);
                M3 = fmaf(u.w, u.w, M3);
            }
            float dot = (A0 + A1) + (A2 + A3);
            float msq = (M0 + M1) + (M2 + M3);
            warp_sum2(dot, msq);
            if (!lane) {
                float e = sqrtf(fmaxf(msq + sq[s] - 2.0f * dot, 0.f));
                D[dst * DS + s] = e;
                D[s * DS + dst] = e;
                if (warp == 0) sq[dst] = msq;     // persist merged norm
                vnxt[warp] = __float_as_uint(e);  // pair (0, 1+warp)
                inxt[warp] = (unsigned)(1 + warp);
            }
        } else if (cnt > 0) {
            // survivor-survivor argmin partials for next config
            const int lok = (lane >= 1) && (lane <= cnt);
            const int sl  = lok ? Lnxt[lane] : 0;
            u64 kk = 0xffffffffffffffffull;
            const int S = 32 - cnt;
            for (int i = 1 + (warp - cnt); i <= cnt - 1; i += S) {
                const int si = Lnxt[i];
                if (lok && lane > i) {
                    float d = D[si * DS + sl];
                    u64 kc = ((u64)__float_as_uint(d) << 32)
                           | (unsigned)((i << 5) | lane);
                    kk = min(kk, kc);
                }
            }
            unsigned kv = (unsigned)(kk >> 32);
            unsigned wv = __reduce_min_sync(FULLM, kv);
            unsigned mm = __ballot_sync(FULLM, kv == wv);
            unsigned ci = ((mm >> lane) & 1) ? (unsigned)(kk & FULLM) : FULLM;
            unsigned wi = __reduce_min_sync(FULLM, ci);
            if (!lane) { vnxt[warp] = wv; inxt[warp] = wi & 0x3ffu; }
        }
        __syncthreads();                          // bar 2
    }

    // final merged row lives at slot Lfinal[0]
    out[(size_t)b * CC + tid] = rows[(Lb + lpar * 32)[0] * CC + tid];
}

extern "C" void kernel_launch(void* const* d_in, const int* in_sizes, int n_in,
                              void* d_out, int out_size)
{
    const float* x  = (const float*)d_in[0];
    const float* cw = (const float*)d_in[1];
    const float* cb = (const float*)d_in[2];
    float* out = (float*)d_out;

    int B = in_sizes[0] / (NN * CC);

    cudaFuncSetAttribute(merge_tree_kernel,
                         cudaFuncAttributeMaxDynamicSharedMemorySize,
                         SMEM_TOTAL);
    merge_tree_kernel<<<B, NT, SMEM_TOTAL>>>(x, cw, cb, out);
}

// round 12
// speedup vs baseline: 1.1758x; 1.0276x over previous
#include <cuda_runtime.h>

#define NN 32
#define DS 33                           // D stride (33 physical slots)
#define CC 1024
#define NT 1024
#define FULLM 0xffffffffu

// dynamic smem layout
#define OFF_ROWS 0                      // float [33][1024]  = 135168
#define OFF_D    135168                 // float [33][33]    = 4356 -> pad 4480
#define OFF_VAL  139648                 // u32   [2][32]     = 256
#define OFF_IDX  139904                 // u32   [2][32]     = 256
#define OFF_SQ   140160                 // float [33]        = 132 -> pad 160
#define OFF_L    140320                 // int   [2][32]     = 256
#define SMEM_TOTAL 140576

typedef unsigned long long u64;

__device__ __forceinline__ float warp_sum(float v) {
    #pragma unroll
    for (int o = 16; o; o >>= 1) v += __shfl_down_sync(FULLM, v, o);
    return v;
}

__device__ __forceinline__ void warp_sum2(float& a, float& b) {
    #pragma unroll
    for (int o = 16; o; o >>= 1) {
        a += __shfl_down_sync(FULLM, a, o);
        b += __shfl_down_sync(FULLM, b, o);
    }
}

__global__ __launch_bounds__(NT, 1)
void merge_tree_kernel(const float* __restrict__ x,
                       const float* __restrict__ cw,
                       const float* __restrict__ cb,
                       float* __restrict__ out)
{
    extern __shared__ unsigned char sm_raw[];
    float*    rows = (float*)(sm_raw + OFF_ROWS);
    float*    D    = (float*)(sm_raw + OFF_D);        // [33][33], stride DS
    unsigned* vals = (unsigned*)(sm_raw + OFF_VAL);   // [2][32]
    unsigned* idxs = (unsigned*)(sm_raw + OFF_IDX);   // [2][32]
    float*    sq   = (float*)(sm_raw + OFF_SQ);       // [33]
    int*      Lb   = (int*)(sm_raw + OFF_L);          // [2][32]

    const int tid  = threadIdx.x;
    const int lane = tid & 31;
    const int warp = tid >> 5;
    const int b    = blockIdx.x;

    // ---- load batch rows (coalesced float4) ----
    {
        const float4* xb4 = (const float4*)(x + (size_t)b * (NN * CC));
        float4* r4 = (float4*)rows;
        #pragma unroll
        for (int i = tid; i < NN * CC / 4; i += NT) r4[i] = xb4[i];
    }
    const float w00 = cw[0], w01 = cw[1], w02 = cw[2];
    const float w10 = cw[3], w11 = cw[4], w12 = cw[5];
    const float bv  = cb[0];
    if (tid < NN) Lb[tid] = tid;                      // L buffer 0
    __syncthreads();

    // ---- cache own row in registers; norms (fp32, 4-chain) ----
    float4 rv[8];
    {
        const float4* r4w = (const float4*)(rows + warp * CC);
        #pragma unroll
        for (int k = 0; k < 8; k++) rv[k] = r4w[lane + 32 * k];
        float a0 = 0, a1 = 0, a2 = 0, a3 = 0;
        #pragma unroll
        for (int k = 0; k < 8; k++) {
            a0 = fmaf(rv[k].x, rv[k].x, a0);
            a1 = fmaf(rv[k].y, rv[k].y, a1);
            a2 = fmaf(rv[k].z, rv[k].z, a2);
            a3 = fmaf(rv[k].w, rv[k].w, a3);
        }
        float s = warp_sum((a0 + a1) + (a2 + a3));
        if (!lane) sq[warp] = s;
    }
    __syncthreads();

    // ---- initial gram, balanced rotation (each unordered pair once;
    //      FMA commutes so values match canonical order) ----
    {
        const float sqi = sq[warp];
        #pragma unroll 1
        for (int k = 1; k <= 16; k++) {
            if (k == 16 && warp >= 16) break;
            const int j = (warp + k) & 31;
            const float4* rj4 = (const float4*)(rows + j * CC);
            float a0 = 0, a1 = 0, a2 = 0, a3 = 0;
            #pragma unroll
            for (int q = 0; q < 8; q++) {
                float4 v = rj4[lane + 32 * q];
                a0 = fmaf(rv[q].x, v.x, a0);
                a1 = fmaf(rv[q].y, v.y, a1);
                a2 = fmaf(rv[q].z, v.z, a2);
                a3 = fmaf(rv[q].w, v.w, a3);
            }
            float dot = warp_sum((a0 + a1) + (a2 + a3));
            if (!lane) {
                float d2 = sqi + sq[j] - 2.0f * dot;
                float d  = sqrtf(fmaxf(d2, 0.f));
                D[warp * DS + j] = d;
                D[j * DS + warp] = d;
            }
        }
    }
    __syncthreads();

    // ---- pre-loop argmin partials into buffer 0 ----
    {
        unsigned kv = FULLM, ki = 0x3ffu;
        if (lane > warp) {
            kv = __float_as_uint(D[warp * DS + lane]);
            ki = (unsigned)((warp << 5) | lane);
        }
        unsigned wv = __reduce_min_sync(FULLM, kv);
        unsigned mm = __ballot_sync(FULLM, kv == wv);
        unsigned ci = ((mm >> lane) & 1) ? ki : FULLM;
        unsigned wi = __reduce_min_sync(FULLM, ci);
        if (!lane) { vals[warp] = wv; idxs[warp] = wi; }
    }
    __syncthreads();

    // ==== 31 merge steps, 2 barriers each (spare-slot, flat P2) ====
    int n = NN;
    int par = 0;        // argmin partial parity
    int lpar = 0;       // L parity
    int spare = 32;     // always-free physical slot
    for (int step = 0; step < NN - 1; step++, n--) {
        unsigned* vcur = vals + par * 32;
        unsigned* icur = idxs + par * 32;
        par ^= 1;
        unsigned* vnxt = vals + par * 32;
        unsigned* inxt = idxs + par * 32;
        int* Lcur = Lb + lpar * 32;
        lpar ^= 1;
        int* Lnxt = Lb + lpar * 32;

        // ---------- P1 ----------
        // combine 32 partials -> global (value, lexicographic idx) min
        unsigned v  = vcur[lane];
        unsigned gm = __reduce_min_sync(FULLM, v);
        unsigned mk = __ballot_sync(FULLM, v == gm);
        unsigned cd = ((mk >> lane) & 1) ? icur[lane] : FULLM;
        unsigned gi = __reduce_min_sync(FULLM, cd);

        const int a   = (gi >> 5) & 31;
        const int bbj = gi & 31;
        const int ra  = Lcur[a];
        const int rb  = Lcur[bbj];
        const int dst = spare;                    // merged row -> spare slot
        // freed slot: normally L[a]; when a==1 the reference's sequential
        // perm-sets drop logical row 0 and KEEP row 1, so freed slot is L[0].
        spare = (a == 1) ? Lcur[0] : ra;

        // conv1d(2ch->1ch,k=3,SAME)+bias+relu, one elem/thread
        const float* Xa = rows + ra * CC;
        const float* Xb = rows + rb * CC;
        const int h = tid;
        float a1v = Xa[h], b1v = Xb[h];
        float a0v = (h > 0)      ? Xa[h - 1] : 0.f;
        float a2v = (h < CC - 1) ? Xa[h + 1] : 0.f;
        float b0v = (h > 0)      ? Xb[h - 1] : 0.f;
        float b2v = (h < CC - 1) ? Xb[h + 1] : 0.f;
        float m = fmaf(w00, a0v, fmaf(w01, a1v, fmaf(w02, a2v,
                  fmaf(w10, b0v, fmaf(w11, b1v, fmaf(w12, b2v, bv))))));
        m = fmaxf(m, 0.f);
        rows[dst * CC + h] = m;                   // no WAR: dst was spare

        if (tid < n - 1) {
            int nv;
            if (tid == 0) nv = dst;
            else {
                int pp  = tid + 1;
                int src = (pp == a) ? 0 : ((pp == bbj) ? 1 : pp);
                nv = Lcur[src];
            }
            Lnxt[tid] = nv;
        }
        __syncthreads();                          // bar 1: rows[dst], Lnxt visible

        // ---------- P2 (flat: each warp <=1 scan row + <=1 dot) ----------
        const int cnt = n - 2;                    // next-config survivors 1..cnt
        if (cnt > 0) {
            // lane-resident survivor slot table, redistributed by shfl
            const int slv = (lane >= 1 && lane <= cnt) ? Lnxt[lane] : 0;

            // scan row i = warp (survivor-survivor pairs of next config):
            // lanes j in (warp, cnt] read D[Lnxt[warp]][Lnxt[j]]
            u64 kk = 0xffffffffffffffffull;
            if (warp >= 1 && warp <= cnt - 1) {
                const int si = __shfl_sync(FULLM, slv, warp);
                unsigned kv = FULLM;
                if (lane > warp && lane <= cnt)
                    kv = __float_as_uint(D[si * DS + slv]);
                unsigned wv = __reduce_min_sync(FULLM, kv);
                unsigned mm = __ballot_sync(FULLM, kv == wv);
                int jw = __ffs(mm) - 1;           // lowest lane = smallest j
                kk = ((u64)wv << 32) | (unsigned)((warp << 5) | jw);
            }

            if (warp < cnt) {
                // survivor dot: dot(m, s) + |m|^2
                const int s = __shfl_sync(FULLM, slv, warp + 1);
                const float4* rm = (const float4*)(rows + dst * CC);
                const float4* rs = (const float4*)(rows + s * CC);
                float A0 = 0, A1 = 0, A2 = 0, A3 = 0;
                float M0 = 0, M1 = 0, M2 = 0, M3 = 0;
                #pragma unroll
                for (int k = 0; k < 8; k++) {
                    float4 u = rm[lane + 32 * k];
                    float4 w = rs[lane + 32 * k];
                    A0 = fmaf(u.x, w.x, A0);
                    A1 = fmaf(u.y, w.y, A1);
                    A2 = fmaf(u.z, w.z, A2);
                    A3 = fmaf(u.w, w.w, A3);
                    M0 = fmaf(u.x, u.x, M0);
                    M1 = fmaf(u.y, u.y, M1);
                    M2 = fmaf(u.z, u.z, M2);
                    M3 = fmaf(u.w, u.w, M3);
                }
                float dot = (A0 + A1) + (A2 + A3);
                float msq = (M0 + M1) + (M2 + M3);
                warp_sum2(dot, msq);
                if (!lane) {
                    float e = sqrtf(fmaxf(msq + sq[s] - 2.0f * dot, 0.f));
                    D[dst * DS + s] = e;          // disjoint from scan reads
                    D[s * DS + dst] = e;
                    if (warp == 0) sq[dst] = msq; // persist merged norm
                    u64 kd = ((u64)__float_as_uint(e) << 32)
                           | (unsigned)(1 + warp);   // pair (0, 1+warp)
                    kk = min(kk, kd);
                }
            }

            if (!lane) {
                vnxt[warp] = (unsigned)(kk >> 32);
                inxt[warp] = (unsigned)(kk & 0x3ffu);
            }
        }
        __syncthreads();                          // bar 2
    }

    // final merged row lives at slot Lfinal[0]
    out[(size_t)b * CC + tid] = rows[(Lb + lpar * 32)[0] * CC + tid];
}

extern "C" void kernel_launch(void* const* d_in, const int* in_sizes, int n_in,
                              void* d_out, int out_size)
{
    const float* x  = (const float*)d_in[0];
    const float* cw = (const float*)d_in[1];
    const float* cb = (const float*)d_in[2];
    float* out = (float*)d_out;

    int B = in_sizes[0] / (NN * CC);

    cudaFuncSetAttribute(merge_tree_kernel,
                         cudaFuncAttributeMaxDynamicSharedMemorySize,
                         SMEM_TOTAL);
    merge_tree_kernel<<<B, NT, SMEM_TOTAL>>>(x, cw, cb, out);
}